// round 13
// baseline (speedup 1.0000x reference)
#include <cuda_runtime.h>
#include <cuda_bf16.h>
#include <cstdint>

#define NPX 1024
#define NE 1984
#define KTOP 256
#define NIMG 24
#define SINK_ITERS 150
#define CLU 4
#define EXIT_TOL 1e-2f
#define MIN_ITERS 20

__device__ float g_v[NIMG][NPX];
__device__ float g_bd[NIMG][2][2][KTOP];
__device__ float g_wpart[NIMG * CLU];
__device__ int g_ctr;

__device__ __forceinline__ unsigned ordf(float f) {
    unsigned u = __float_as_uint(f);
    return (u & 0x80000000u) ? ~u : (u | 0x80000000u);
}

__device__ __forceinline__ float blkMax(float v, float* r8) {
    #pragma unroll
    for (int o = 16; o; o >>= 1) v = fmaxf(v, __shfl_xor_sync(0xffffffffu, v, o));
    if ((threadIdx.x & 31) == 0) r8[threadIdx.x >> 5] = v;
    __syncthreads();
    float m = r8[0];
    #pragma unroll
    for (int k = 1; k < 8; ++k) m = fmaxf(m, r8[k]);
    __syncthreads();
    return m;
}
__device__ __forceinline__ float blkSum(float v, float* r8) {
    #pragma unroll
    for (int o = 16; o; o >>= 1) v += __shfl_xor_sync(0xffffffffu, v, o);
    if ((threadIdx.x & 31) == 0) r8[threadIdx.x >> 5] = v;
    __syncthreads();
    float s = r8[0];
    #pragma unroll
    for (int k = 1; k < 8; ++k) s += r8[k];
    __syncthreads();
    return s;
}

__device__ __forceinline__ void edge_uv(int e, int& u, int& v) {
    if (e < 992) { int rr = e / 31, cc = e - rr * 31; u = rr * 32 + cc; v = u + 1; }
    else { u = e - 992; v = u + 32; }
}

__device__ void bitonic2048(unsigned long long* keys) {
    int tid = threadIdx.x;
    for (unsigned k = 2; k <= 2048; k <<= 1)
        for (unsigned j = k >> 1; j > 0; j >>= 1) {
            __syncthreads();
            for (unsigned i = tid; i < 2048; i += 256) {
                unsigned l = i ^ j;
                if (l > i) {
                    unsigned long long a = keys[i], b = keys[l];
                    bool up = ((i & k) == 0);
                    if ((a > b) == up) { keys[i] = b; keys[l] = a; }
                }
            }
        }
    __syncthreads();
}

__device__ __forceinline__ uint32_t smem_u32(const void* p) {
    uint32_t a;
    asm("{ .reg .u64 t; cvta.to.shared.u64 t, %1; cvt.u32.u64 %0, t; }" : "=r"(a) : "l"(p));
    return a;
}
__device__ __forceinline__ void st_cluster_f32(uint32_t addr, int rank, float v) {
    uint32_t r;
    asm volatile("mapa.shared::cluster.u32 %0, %1, %2;" : "=r"(r) : "r"(addr), "r"(rank));
    asm volatile("st.shared::cluster.b32 [%0], %1;" :: "r"(r), "f"(v) : "memory");
}
#define CLUSTER_SYNC() do { \
    asm volatile("barrier.cluster.arrive.aligned;" ::: "memory"); \
    asm volatile("barrier.cluster.wait.aligned;" ::: "memory"); } while (0)

// ---------------- stage 1: softmax + one-hot + pool (float4 loads) ----------------
__global__ void pool_kernel(const float* __restrict__ x, const int* __restrict__ y) {
    int idx = blockIdx.x * blockDim.x + threadIdx.x;
    if (idx >= NIMG * NPX) return;
    int m = idx >> 10, cell = idx & 1023;
    int gi = cell >> 5, gj = cell & 31;
    float acc = 0.f;
    if (m < 12) {
        int b = m / 3, c = m % 3 + 1;
        const float* xb = x + (size_t)b * 4 * 65536;
        for (int pi = 0; pi < 8; ++pi) {
            int off0 = (gi * 8 + pi) * 256 + gj * 8;
            #pragma unroll
            for (int h = 0; h < 2; ++h) {
                int off = off0 + h * 4;
                float4 v0 = *(const float4*)(xb + off);
                float4 v1 = *(const float4*)(xb + 65536 + off);
                float4 v2 = *(const float4*)(xb + 131072 + off);
                float4 v3 = *(const float4*)(xb + 196608 + off);
                const float* p0 = &v0.x; const float* p1 = &v1.x;
                const float* p2 = &v2.x; const float* p3 = &v3.x;
                #pragma unroll
                for (int j = 0; j < 4; ++j) {
                    float x0 = p0[j], x1 = p1[j], x2 = p2[j], x3 = p3[j];
                    float mx = fmaxf(fmaxf(x0, x1), fmaxf(x2, x3));
                    float e0 = __expf(x0 - mx), e1 = __expf(x1 - mx),
                          e2 = __expf(x2 - mx), e3 = __expf(x3 - mx);
                    float ec = (c == 1) ? e1 : ((c == 2) ? e2 : e3);
                    acc += ec / (e0 + e1 + e2 + e3);
                }
            }
        }
    } else {
        int mm = m - 12, b = mm / 3, c = mm % 3 + 1;
        const int* yb = y + (size_t)b * 65536;
        int cnt = 0;
        for (int pi = 0; pi < 8; ++pi) {
            int off0 = (gi * 8 + pi) * 256 + gj * 8;
            #pragma unroll
            for (int h = 0; h < 2; ++h) {
                int4 yv = *(const int4*)(yb + off0 + h * 4);
                cnt += (yv.x == c) + (yv.y == c) + (yv.z == c) + (yv.w == c);
            }
        }
        acc = (float)cnt;
    }
    g_v[m][cell] = acc * 0.015625f;
}

// ---------------- stage 2: persistence diagrams ----------------
__global__ void diagram_kernel() {
    int m = blockIdx.x >> 1;
    int r = blockIdx.x & 1;
    __shared__ float v[NPX];
    __shared__ unsigned long long keys[2048];
    __shared__ float bArr[2048], dArr[2048];
    __shared__ int parent[NPX];
    __shared__ float r8[8];
    __shared__ int2 sR[32];
    __shared__ float2 sB[32];
    __shared__ float sW[32];
    int tid = threadIdx.x;

    for (int i = tid; i < NPX; i += 256) {
        float val = g_v[m][i];
        if (r) val = -val;
        v[i] = val; parent[i] = i;
    }
    __syncthreads();

    for (int e = tid; e < 2048; e += 256) {
        unsigned long long key = ~0ULL;
        if (e < NE) {
            int u, w2; edge_uv(e, u, w2);
            float w = fmaxf(v[u], v[w2]);
            key = ((unsigned long long)ordf(w) << 32) | (unsigned)e;
        }
        keys[e] = key;
    }
    float mn = v[tid], mx = v[tid];
    for (int i = tid + 256; i < NPX; i += 256) { mn = fminf(mn, v[i]); mx = fmaxf(mx, v[i]); }

    bitonic2048(keys);
    float vmax = blkMax(mx, r8);
    float vmin = -blkMax(-mn, r8);

    if (tid < 32) {
        for (int base = 0; base < NE; base += 32) {
            int s = base + tid;
            int e = (int)(unsigned)keys[s];
            int u, vv; edge_uv(e, u, vv);
            float w = fmaxf(v[u], v[vv]);
            int ru = u;
            for (;;) { int p = parent[ru]; if (p == ru) break;
                       int g2 = parent[p]; parent[ru] = g2; ru = g2; }
            int rv = vv;
            for (;;) { int p = parent[rv]; if (p == rv) break;
                       int g2 = parent[p]; parent[rv] = g2; rv = g2; }
            sR[tid] = make_int2(ru, rv);
            sB[tid] = make_float2(v[ru], v[rv]);
            sW[tid] = w;
            __syncwarp();
            if (tid == 0) {
                #pragma unroll 4
                for (int l = 0; l < 32; ++l) {
                    int2 rr2 = sR[l];
                    float wl = sW[l];
                    float b, d;
                    if (rr2.x == rr2.y) { b = wl; d = wl; }
                    else {
                        int ra = rr2.x, rb = rr2.y;
                        float2 bb0 = sB[l];
                        float ba = bb0.x, bb2 = bb0.y;
                        int pa = parent[ra];
                        int pb2 = parent[rb];
                        if (pa != ra) {
                            do { ra = pa; pa = parent[ra]; } while (pa != ra);
                            ba = v[ra];
                        }
                        if (pb2 != rb) {
                            do { rb = pb2; pb2 = parent[rb]; } while (pb2 != rb);
                            bb2 = v[rb];
                        }
                        if (ra == rb) { b = wl; d = wl; }
                        else {
                            b = fmaxf(ba, bb2); d = wl;
                            if (ba <= bb2) parent[rb] = ra;
                            else           parent[ra] = rb;
                        }
                    }
                    bArr[base + l] = b; dArr[base + l] = d;
                }
            }
            __syncwarp();
        }
        if (tid == 0 && r == 0) { bArr[NE] = vmin; dArr[NE] = vmax; }
    }
    __syncthreads();

    int limit = (r == 0) ? NE + 1 : NE;
    for (int e = tid; e < 2048; e += 256) {
        unsigned long long key = ~0ULL;
        if (e < limit) {
            float pval = dArr[e] - bArr[e];
            key = ((unsigned long long)(~ordf(pval)) << 32) | (unsigned)e;
        }
        keys[e] = key;
    }
    bitonic2048(keys);

    if (tid < KTOP) {
        int s = (int)(unsigned)keys[tid];
        if (r == 0) {
            g_bd[m][0][0][tid] = bArr[s];
            g_bd[m][0][1][tid] = dArr[s];
        } else {
            g_bd[m][1][0][tid] = -dArr[s];
            g_bd[m][1][1][tid] = -bArr[s];
        }
    }
}

// ---------------- stage 3: factorized clustered Sinkhorn ----------------
#define OFF_PBF 0
#define OFF_PBG 1024
#define OFF_F   2048
#define OFF_G   2304
#define OFF_EXG 2560
#define OFF_EXF 2816
#define OFF_EDA 3072
#define OFF_EDB 3328
#define OFF_DAS 3584
#define OFF_DBS 3840
#define OFF_A   4096
#define OFF_B   4608
#define OFF_RED 5120
#define OFF_RED2 5128
#define OFF_SC  5136
#define SINK_SMEM_FLOATS 5140

__global__ void __cluster_dims__(CLU, 1, 1) __launch_bounds__(256, 1)
sinkhorn_kernel(float* __restrict__ out) {
    extern __shared__ float sm[];
    float* pbf = sm + OFF_PBF;
    float* pbg = sm + OFF_PBG;
    float* F = sm + OFF_F;
    float* G = sm + OFF_G;
    float* EG = sm + OFF_EXG;
    float* EF = sm + OFF_EXF;
    float* EDA = sm + OFF_EDA;
    float* EDB = sm + OFF_EDB;
    float* das = sm + OFF_DAS;
    float* dbs = sm + OFF_DBS;
    float2* Ash = (float2*)(sm + OFF_A);
    float2* Bsh = (float2*)(sm + OFF_B);
    float* r8 = sm + OFF_RED;
    float* r8d = sm + OFF_RED2;
    float* sc = sm + OFF_SC;

    int t = threadIdx.x;
    int w = t >> 5;
    int p = blockIdx.x >> 2;
    int q = blockIdx.x & 3;
    int q64 = q * 64;
    int dim = (p < 12) ? 0 : 1;
    int img = (p < 12) ? p : p - 12;

    float ab = g_bd[img][dim][0][t],      ad = g_bd[img][dim][1][t];
    float bb = g_bd[12 + img][dim][0][t], bd = g_bd[12 + img][dim][1][t];
    float2 a = make_float2(ab, ad), b = make_float2(bb, bd);
    Ash[t] = a; Bsh[t] = b;
    float da = 0.5f * (ad - ab), db = 0.5f * (bd - bb);
    if (t < 4) sc[t] = (t < 2) ? 0.f : 1.f;
    EG[t] = 1.f;
    __syncthreads();

    float mC = fmaxf(da, db);
    #pragma unroll 4
    for (int i = 0; i < KTOP; ++i) {
        float2 aq = Ash[i];
        mC = fmaxf(mC, fmaxf(fabsf(aq.x - b.x), fabsf(aq.y - b.y)));
    }
    float eps = 0.02f * fmaxf(blkMax(mC, r8), 1e-6f);
    float ie = 1.f / eps;
    das[t] = da * ie; dbs[t] = db * ie;
    EDA[t] = __expf(-da * ie); EDB[t] = __expf(-db * ie);

    float4 rEf[16], rEg[16];
    #pragma unroll
    for (int k = 0; k < 16; ++k) {
        float2 b0 = Bsh[q64 + k * 4 + 0], b1 = Bsh[q64 + k * 4 + 1],
               b2 = Bsh[q64 + k * 4 + 2], b3 = Bsh[q64 + k * 4 + 3];
        rEf[k].x = __expf(-fmaxf(fabsf(a.x - b0.x), fabsf(a.y - b0.y)) * ie);
        rEf[k].y = __expf(-fmaxf(fabsf(a.x - b1.x), fabsf(a.y - b1.y)) * ie);
        rEf[k].z = __expf(-fmaxf(fabsf(a.x - b2.x), fabsf(a.y - b2.y)) * ie);
        rEf[k].w = __expf(-fmaxf(fabsf(a.x - b3.x), fabsf(a.y - b3.y)) * ie);
        float2 a0 = Ash[q64 + k * 4 + 0], a1 = Ash[q64 + k * 4 + 1],
               a2 = Ash[q64 + k * 4 + 2], a3 = Ash[q64 + k * 4 + 3];
        rEg[k].x = __expf(-fmaxf(fabsf(a0.x - b.x), fabsf(a0.y - b.y)) * ie);
        rEg[k].y = __expf(-fmaxf(fabsf(a1.x - b.x), fabsf(a1.y - b.y)) * ie);
        rEg[k].z = __expf(-fmaxf(fabsf(a2.x - b.x), fabsf(a2.y - b.y)) * ie);
        rEg[k].w = __expf(-fmaxf(fabsf(a3.x - b.x), fabsf(a3.y - b.y)) * ie);
    }
    __syncthreads();
    CLUSTER_SYNC();

    uint32_t pbf_addr = smem_u32(&pbf[q * 256 + t]);
    uint32_t pbg_addr = smem_u32(&pbg[q * 256 + t]);
    float K_G = 0.f, K_F = 0.f;
    float myEDA = EDA[t], myEDB = EDB[t];
    float gOld = 0.f;
    float phiF = 0.f, phiG = 0.f;
    const float4* EGv = (const float4*)(EG + q64);
    const float4* EFv = (const float4*)(EF + q64);

    for (int it = 0; it < SINK_ITERS; ++it) {
        bool doK = (it < 16) || ((it & 3) == 0);
        // ---- f half-iter ----
        float4 acc = make_float4(0.f, 0.f, 0.f, 0.f);
        #pragma unroll
        for (int k = 0; k < 16; ++k) {
            float4 g4 = EGv[k];
            acc.x = fmaf(g4.x, rEf[k].x, acc.x);
            acc.y = fmaf(g4.y, rEf[k].y, acc.y);
            acc.z = fmaf(g4.z, rEf[k].z, acc.z);
            acc.w = fmaf(g4.w, rEf[k].w, acc.w);
        }
        float s = (acc.x + acc.y) + (acc.z + acc.w);
        #pragma unroll
        for (int rr = 0; rr < CLU; ++rr) st_cluster_f32(pbf_addr, rr, s);
        if (t < 32) {
            float s2 = 0.f;
            #pragma unroll
            for (int k = 0; k < 8; ++k) { int j = t + k * 32; s2 = fmaf(EG[j], EDB[j], s2); }
            #pragma unroll
            for (int o = 16; o; o >>= 1) s2 += __shfl_xor_sync(0xffffffffu, s2, o);
            if (t == 0) sc[0] = -(K_G + __logf(s2 + 256.f * sc[3]));
        }
        CLUSTER_SYNC();
        {
            float S = ((pbf[t] + pbf[256 + t]) + (pbf[512 + t] + pbf[768 + t]))
                    + 256.f * sc[3] * myEDA;
            phiF = -(K_G + __logf(S));
        }
        if (doK) {
            float m2 = phiF;
            #pragma unroll
            for (int o = 16; o; o >>= 1) m2 = fmaxf(m2, __shfl_xor_sync(0xffffffffu, m2, o));
            if ((t & 31) == 0) r8[w] = m2;
            __syncthreads();
            K_F = r8[0];
            #pragma unroll
            for (int k = 1; k < 8; ++k) K_F = fmaxf(K_F, r8[k]);
        }
        EF[t] = __expf(phiF - K_F);
        if (t == 0) sc[2] = __expf(sc[0] - K_F);
        __syncthreads();

        // ---- g half-iter ----
        acc = make_float4(0.f, 0.f, 0.f, 0.f);
        #pragma unroll
        for (int k = 0; k < 16; ++k) {
            float4 f4 = EFv[k];
            acc.x = fmaf(f4.x, rEg[k].x, acc.x);
            acc.y = fmaf(f4.y, rEg[k].y, acc.y);
            acc.z = fmaf(f4.z, rEg[k].z, acc.z);
            acc.w = fmaf(f4.w, rEg[k].w, acc.w);
        }
        s = (acc.x + acc.y) + (acc.z + acc.w);
        #pragma unroll
        for (int rr = 0; rr < CLU; ++rr) st_cluster_f32(pbg_addr, rr, s);
        if (t < 32) {
            float s2 = 0.f;
            #pragma unroll
            for (int k = 0; k < 8; ++k) { int i = t + k * 32; s2 = fmaf(EF[i], EDA[i], s2); }
            #pragma unroll
            for (int o = 16; o; o >>= 1) s2 += __shfl_xor_sync(0xffffffffu, s2, o);
            if (t == 0) sc[1] = -(K_F + __logf(s2 + 256.f * sc[2]));
        }
        CLUSTER_SYNC();
        {
            float S = ((pbg[t] + pbg[256 + t]) + (pbg[512 + t] + pbg[768 + t]))
                    + 256.f * sc[2] * myEDB;
            phiG = -(K_F + __logf(S));
        }
        float maxd = 1e30f;
        if (doK) {
            float dlt = fabsf(phiG - gOld);
            gOld = phiG;
            float m2 = phiG;
            #pragma unroll
            for (int o = 16; o; o >>= 1) {
                m2 = fmaxf(m2, __shfl_xor_sync(0xffffffffu, m2, o));
                dlt = fmaxf(dlt, __shfl_xor_sync(0xffffffffu, dlt, o));
            }
            if ((t & 31) == 0) { r8[w] = m2; r8d[w] = dlt; }
            __syncthreads();
            K_G = r8[0]; maxd = r8d[0];
            #pragma unroll
            for (int k = 1; k < 8; ++k) {
                K_G = fmaxf(K_G, r8[k]);
                maxd = fmaxf(maxd, r8d[k]);
            }
        }
        EG[t] = __expf(phiG - K_G);
        if (t == 0) sc[3] = __expf(sc[1] - K_G);
        __syncthreads();
        if (doK && it >= MIN_ITERS && maxd < EXIT_TOL) break;
    }

    F[t] = phiF; G[t] = phiG;
    __syncthreads();

    // ---- final cost partial ----
    float acc2 = 0.f;
    float myG = phiG;
    #pragma unroll 4
    for (int ii = 0; ii < 64; ++ii) {
        float2 aq = Ash[q64 + ii];
        float cs = fmaxf(fabsf(aq.x - b.x), fabsf(aq.y - b.y)) * ie;
        acc2 += __expf(F[q64 + ii] + myG - cs) * cs;
    }
    if (t < 64) {
        int i = q64 + t;
        acc2 += 256.f * __expf(F[i] + sc[1] - das[i]) * das[i];
        acc2 += 256.f * __expf(sc[0] + G[i] - dbs[i]) * dbs[i];
    }
    float tot = blkSum(acc2, r8);

    if (t == 0) {
        g_wpart[p * CLU + q] = tot * eps;
        __threadfence();
        int ticket = atomicAdd(&g_ctr, 1);
        if (ticket == NIMG * CLU - 1) {
            g_ctr = 0;
            float ssum = 0.f;
            for (int pp = 0; pp < NIMG; ++pp) {
                float w2 = 0.f;
                for (int qq = 0; qq < CLU; ++qq) w2 += g_wpart[pp * CLU + qq];
                ssum += w2;
            }
            out[0] = ssum * 0.25f;
        }
    }
}

extern "C" void kernel_launch(void* const* d_in, const int* in_sizes, int n_in,
                              void* d_out, int out_size) {
    (void)in_sizes; (void)n_in; (void)out_size;
    const float* x = (const float*)d_in[0];
    const int* y = (const int*)d_in[1];
    static bool attr_set = false;
    if (!attr_set) {
        cudaFuncSetAttribute(sinkhorn_kernel,
                             cudaFuncAttributeMaxDynamicSharedMemorySize,
                             SINK_SMEM_FLOATS * 4);
        attr_set = true;
    }
    pool_kernel<<<(NIMG * NPX + 255) / 256, 256>>>(x, y);
    diagram_kernel<<<48, 256>>>();
    sinkhorn_kernel<<<NIMG * CLU, 256, SINK_SMEM_FLOATS * 4>>>((float*)d_out);
}

// round 14
// speedup vs baseline: 1.0059x; 1.0059x over previous
#include <cuda_runtime.h>
#include <cuda_bf16.h>
#include <cstdint>

#define NPX 1024
#define NE 1984
#define KTOP 256
#define NIMG 24
#define SINK_ITERS 150
#define CLU 4
#define EXIT_TOL 1e-2f
#define MIN_ITERS 20

__device__ float g_v[NIMG][NPX];
__device__ float g_bd[NIMG][2][2][KTOP];
__device__ float g_wpart[NIMG * CLU];
__device__ int g_ctr;

__device__ __forceinline__ unsigned ordf(float f) {
    unsigned u = __float_as_uint(f);
    return (u & 0x80000000u) ? ~u : (u | 0x80000000u);
}

__device__ __forceinline__ float blkMax(float v, float* r8) {
    #pragma unroll
    for (int o = 16; o; o >>= 1) v = fmaxf(v, __shfl_xor_sync(0xffffffffu, v, o));
    if ((threadIdx.x & 31) == 0) r8[threadIdx.x >> 5] = v;
    __syncthreads();
    float m = r8[0];
    #pragma unroll
    for (int k = 1; k < 8; ++k) m = fmaxf(m, r8[k]);
    __syncthreads();
    return m;
}
__device__ __forceinline__ float blkSum(float v, float* r8) {
    #pragma unroll
    for (int o = 16; o; o >>= 1) v += __shfl_xor_sync(0xffffffffu, v, o);
    if ((threadIdx.x & 31) == 0) r8[threadIdx.x >> 5] = v;
    __syncthreads();
    float s = r8[0];
    #pragma unroll
    for (int k = 1; k < 8; ++k) s += r8[k];
    __syncthreads();
    return s;
}

__device__ __forceinline__ void edge_uv(int e, int& u, int& v) {
    if (e < 992) { int rr = e / 31, cc = e - rr * 31; u = rr * 32 + cc; v = u + 1; }
    else { u = e - 992; v = u + 32; }
}

__device__ void bitonic2048(unsigned long long* keys) {
    int tid = threadIdx.x;
    for (unsigned k = 2; k <= 2048; k <<= 1)
        for (unsigned j = k >> 1; j > 0; j >>= 1) {
            __syncthreads();
            for (unsigned i = tid; i < 2048; i += 256) {
                unsigned l = i ^ j;
                if (l > i) {
                    unsigned long long a = keys[i], b = keys[l];
                    bool up = ((i & k) == 0);
                    if ((a > b) == up) { keys[i] = b; keys[l] = a; }
                }
            }
        }
    __syncthreads();
}

__device__ __forceinline__ uint32_t smem_u32(const void* p) {
    uint32_t a;
    asm("{ .reg .u64 t; cvta.to.shared.u64 t, %1; cvt.u32.u64 %0, t; }" : "=r"(a) : "l"(p));
    return a;
}
__device__ __forceinline__ void st_cluster_f32(uint32_t addr, int rank, float v) {
    uint32_t r;
    asm volatile("mapa.shared::cluster.u32 %0, %1, %2;" : "=r"(r) : "r"(addr), "r"(rank));
    asm volatile("st.shared::cluster.b32 [%0], %1;" :: "r"(r), "f"(v) : "memory");
}
#define CLUSTER_SYNC() do { \
    asm volatile("barrier.cluster.arrive.aligned;" ::: "memory"); \
    asm volatile("barrier.cluster.wait.aligned;" ::: "memory"); } while (0)

// ---------------- stage 1: softmax + one-hot + pool ----------------
__global__ void pool_kernel(const float* __restrict__ x, const int* __restrict__ y) {
    int idx = blockIdx.x * blockDim.x + threadIdx.x;
    if (idx >= NIMG * NPX) return;
    int m = idx >> 10, cell = idx & 1023;
    int gi = cell >> 5, gj = cell & 31;
    float acc = 0.f;
    if (m < 12) {
        int b = m / 3, c = m % 3 + 1;
        const float* xb = x + (size_t)b * 4 * 65536;
        for (int pi = 0; pi < 8; ++pi) {
            int off0 = (gi * 8 + pi) * 256 + gj * 8;
            #pragma unroll
            for (int h = 0; h < 2; ++h) {
                int off = off0 + h * 4;
                float4 v0 = *(const float4*)(xb + off);
                float4 v1 = *(const float4*)(xb + 65536 + off);
                float4 v2 = *(const float4*)(xb + 131072 + off);
                float4 v3 = *(const float4*)(xb + 196608 + off);
                const float* p0 = &v0.x; const float* p1 = &v1.x;
                const float* p2 = &v2.x; const float* p3 = &v3.x;
                #pragma unroll
                for (int j = 0; j < 4; ++j) {
                    float x0 = p0[j], x1 = p1[j], x2 = p2[j], x3 = p3[j];
                    float mx = fmaxf(fmaxf(x0, x1), fmaxf(x2, x3));
                    float e0 = __expf(x0 - mx), e1 = __expf(x1 - mx),
                          e2 = __expf(x2 - mx), e3 = __expf(x3 - mx);
                    float ec = (c == 1) ? e1 : ((c == 2) ? e2 : e3);
                    acc += ec / (e0 + e1 + e2 + e3);
                }
            }
        }
    } else {
        int mm = m - 12, b = mm / 3, c = mm % 3 + 1;
        const int* yb = y + (size_t)b * 65536;
        int cnt = 0;
        for (int pi = 0; pi < 8; ++pi) {
            int off0 = (gi * 8 + pi) * 256 + gj * 8;
            #pragma unroll
            for (int h = 0; h < 2; ++h) {
                int4 yv = *(const int4*)(yb + off0 + h * 4);
                cnt += (yv.x == c) + (yv.y == c) + (yv.z == c) + (yv.w == c);
            }
        }
        acc = (float)cnt;
    }
    g_v[m][cell] = acc * 0.015625f;
}

// ---------------- stage 2: persistence diagrams ----------------
__global__ void diagram_kernel() {
    int m = blockIdx.x >> 1;
    int r = blockIdx.x & 1;
    __shared__ float v[NPX];
    __shared__ unsigned long long keys[2048];
    __shared__ float bArr[2048], dArr[2048];
    __shared__ int parent[NPX];
    __shared__ float r8[8];
    __shared__ int2 sR[32];
    __shared__ float2 sB[32];
    __shared__ float sW[32];
    int tid = threadIdx.x;

    for (int i = tid; i < NPX; i += 256) {
        float val = g_v[m][i];
        if (r) val = -val;
        v[i] = val; parent[i] = i;
    }
    __syncthreads();

    for (int e = tid; e < 2048; e += 256) {
        unsigned long long key = ~0ULL;
        if (e < NE) {
            int u, w2; edge_uv(e, u, w2);
            float w = fmaxf(v[u], v[w2]);
            key = ((unsigned long long)ordf(w) << 32) | (unsigned)e;
        }
        keys[e] = key;
    }
    float mn = v[tid], mx = v[tid];
    for (int i = tid + 256; i < NPX; i += 256) { mn = fminf(mn, v[i]); mx = fmaxf(mx, v[i]); }

    bitonic2048(keys);
    float vmax = blkMax(mx, r8);
    float vmin = -blkMax(-mn, r8);

    if (tid < 32) {
        for (int base = 0; base < NE; base += 32) {
            int s = base + tid;
            int e = (int)(unsigned)keys[s];
            int u, vv; edge_uv(e, u, vv);
            float w = fmaxf(v[u], v[vv]);
            int ru = u;
            for (;;) { int p = parent[ru]; if (p == ru) break;
                       int g2 = parent[p]; parent[ru] = g2; ru = g2; }
            int rv = vv;
            for (;;) { int p = parent[rv]; if (p == rv) break;
                       int g2 = parent[p]; parent[rv] = g2; rv = g2; }
            sR[tid] = make_int2(ru, rv);
            sB[tid] = make_float2(v[ru], v[rv]);
            sW[tid] = w;
            __syncwarp();
            if (tid == 0) {
                #pragma unroll 4
                for (int l = 0; l < 32; ++l) {
                    int2 rr2 = sR[l];
                    float wl = sW[l];
                    float b, d;
                    if (rr2.x == rr2.y) { b = wl; d = wl; }
                    else {
                        int ra = rr2.x, rb = rr2.y;
                        float2 bb0 = sB[l];
                        float ba = bb0.x, bb2 = bb0.y;
                        int pa = parent[ra];
                        int pb2 = parent[rb];
                        if (pa != ra) {
                            do { ra = pa; pa = parent[ra]; } while (pa != ra);
                            ba = v[ra];
                        }
                        if (pb2 != rb) {
                            do { rb = pb2; pb2 = parent[rb]; } while (pb2 != rb);
                            bb2 = v[rb];
                        }
                        if (ra == rb) { b = wl; d = wl; }
                        else {
                            b = fmaxf(ba, bb2); d = wl;
                            if (ba <= bb2) parent[rb] = ra;
                            else           parent[ra] = rb;
                        }
                    }
                    bArr[base + l] = b; dArr[base + l] = d;
                }
            }
            __syncwarp();
        }
        if (tid == 0 && r == 0) { bArr[NE] = vmin; dArr[NE] = vmax; }
    }
    __syncthreads();

    int limit = (r == 0) ? NE + 1 : NE;
    for (int e = tid; e < 2048; e += 256) {
        unsigned long long key = ~0ULL;
        if (e < limit) {
            float pval = dArr[e] - bArr[e];
            key = ((unsigned long long)(~ordf(pval)) << 32) | (unsigned)e;
        }
        keys[e] = key;
    }
    bitonic2048(keys);

    if (tid < KTOP) {
        int s = (int)(unsigned)keys[tid];
        if (r == 0) {
            g_bd[m][0][0][tid] = bArr[s];
            g_bd[m][0][1][tid] = dArr[s];
        } else {
            g_bd[m][1][0][tid] = -dArr[s];
            g_bd[m][1][1][tid] = -bArr[s];
        }
    }
}

// ---------------- stage 3: one-barrier clustered Sinkhorn ----------------
// Rank q owns ROWS [64q,64q+64). f-step: 4 threads/row, intra-CTA combine
// only (no cluster exchange). g-step: column partials over own rows +
// per-rank K_F scalar -> ONE cluster barrier/iter. Double-buffered exchange
// (parity) restores WAR safety that the removed second barrier provided.
__global__ void __cluster_dims__(CLU, 1, 1) __launch_bounds__(256, 1)
sinkhorn_kernel(float* __restrict__ out) {
    __shared__ float pbgB[2][CLU * 256];
    __shared__ float kslotB[2][CLU], pg2B[2][CLU];
    __shared__ float spf[4 * 64];
    __shared__ float fphi[64], efo[64];
    __shared__ float EG[256], Gs[256];
    __shared__ float EDA[256], EDB[256], das[256], dbs[256];
    __shared__ float2 Ash[256], Bsh[256];
    __shared__ float r8[8], r8d[8];
    __shared__ float wv[4];
    __shared__ float sc[4];     // 0=F2, 1=G2, 2=wF2(=256exp(F2-Km)), 3=EG2
    __shared__ float kmS;

    int t = threadIdx.x;
    int w = t >> 5;
    int r = t & 63;             // row-within-chunk for f-phase
    int cc = t >> 6;            // col-chunk for f-phase
    int p = blockIdx.x >> 2;
    int q = blockIdx.x & 3;
    int q64 = q * 64;
    int dim = (p < 12) ? 0 : 1;
    int img = (p < 12) ? p : p - 12;

    float ab = g_bd[img][dim][0][t],      ad = g_bd[img][dim][1][t];
    float bb = g_bd[12 + img][dim][0][t], bd = g_bd[12 + img][dim][1][t];
    float2 a = make_float2(ab, ad), b = make_float2(bb, bd);
    Ash[t] = a; Bsh[t] = b;
    float da = 0.5f * (ad - ab), db = 0.5f * (bd - bb);
    EG[t] = 1.f;
    if (t < 4) sc[t] = (t < 2) ? 0.f : 1.f;   // F2=G2=0, wF2 unused yet, EG2=1
    __syncthreads();

    float mC = fmaxf(da, db);
    #pragma unroll 4
    for (int i = 0; i < KTOP; ++i) {
        float2 aq = Ash[i];
        mC = fmaxf(mC, fmaxf(fabsf(aq.x - b.x), fabsf(aq.y - b.y)));
    }
    float eps = 0.02f * fmaxf(blkMax(mC, r8), 1e-6f);
    float ie = 1.f / eps;
    das[t] = da * ie; dbs[t] = db * ie;
    EDA[t] = __expf(-da * ie); EDB[t] = __expf(-db * ie);
    __syncthreads();

    // Register E: rEf = rows q64+r, cols [64cc,64cc+64); rEg = col t, rows q64+..
    float2 ar = Ash[q64 + r];
    int cb = cc * 64;
    float4 rEf[16], rEg[16];
    #pragma unroll
    for (int k = 0; k < 16; ++k) {
        float2 b0 = Bsh[cb + k * 4 + 0], b1 = Bsh[cb + k * 4 + 1],
               b2 = Bsh[cb + k * 4 + 2], b3 = Bsh[cb + k * 4 + 3];
        rEf[k].x = __expf(-fmaxf(fabsf(ar.x - b0.x), fabsf(ar.y - b0.y)) * ie);
        rEf[k].y = __expf(-fmaxf(fabsf(ar.x - b1.x), fabsf(ar.y - b1.y)) * ie);
        rEf[k].z = __expf(-fmaxf(fabsf(ar.x - b2.x), fabsf(ar.y - b2.y)) * ie);
        rEf[k].w = __expf(-fmaxf(fabsf(ar.x - b3.x), fabsf(ar.y - b3.y)) * ie);
        float2 a0 = Ash[q64 + k * 4 + 0], a1 = Ash[q64 + k * 4 + 1],
               a2 = Ash[q64 + k * 4 + 2], a3 = Ash[q64 + k * 4 + 3];
        rEg[k].x = __expf(-fmaxf(fabsf(a0.x - b.x), fabsf(a0.y - b.y)) * ie);
        rEg[k].y = __expf(-fmaxf(fabsf(a1.x - b.x), fabsf(a1.y - b.y)) * ie);
        rEg[k].z = __expf(-fmaxf(fabsf(a2.x - b.x), fabsf(a2.y - b.y)) * ie);
        rEg[k].w = __expf(-fmaxf(fabsf(a3.x - b.x), fabsf(a3.y - b.y)) * ie);
    }
    CLUSTER_SYNC();

    uint32_t pbg_addr[2] = { smem_u32(&pbgB[0][q * 256 + t]),
                             smem_u32(&pbgB[1][q * 256 + t]) };
    float K_G = 0.f;
    float gOld = 0.f, phiG = 0.f;
    const float4* EGv = (const float4*)(EG + cb);
    const float4* EFOv = (const float4*)efo;

    for (int it = 0; it < SINK_ITERS; ++it) {
        int par = it & 1;
        bool doK = (it < 16) || ((it & 3) == 0);

        // ---- f-step: own rows, intra-CTA only ----
        float4 acc = make_float4(0.f, 0.f, 0.f, 0.f);
        #pragma unroll
        for (int k = 0; k < 16; ++k) {
            float4 g4 = EGv[k];
            acc.x = fmaf(g4.x, rEf[k].x, acc.x);
            acc.y = fmaf(g4.y, rEf[k].y, acc.y);
            acc.z = fmaf(g4.z, rEf[k].z, acc.z);
            acc.w = fmaf(g4.w, rEf[k].w, acc.w);
        }
        spf[cc * 64 + r] = (acc.x + acc.y) + (acc.z + acc.w);
        if (t < 32) {                          // F2 from replicated EG
            float s2 = 0.f;
            #pragma unroll
            for (int k = 0; k < 8; ++k) { int j = t + k * 32; s2 = fmaf(EG[j], EDB[j], s2); }
            #pragma unroll
            for (int o = 16; o; o >>= 1) s2 += __shfl_xor_sync(0xffffffffu, s2, o);
            if (t == 0) sc[0] = -(K_G + __logf(s2 + 256.f * sc[3]));
        }
        __syncthreads();                       // S1
        float Kq = 0.f;
        if (t < 64) {
            float S = ((spf[r] + spf[64 + r]) + (spf[128 + r] + spf[192 + r]))
                    + 256.f * sc[3] * EDA[q64 + r];
            float ph = -(K_G + __logf(S));
            fphi[r] = ph;
            float m2 = ph;
            #pragma unroll
            for (int o = 16; o; o >>= 1) m2 = fmaxf(m2, __shfl_xor_sync(0xffffffffu, m2, o));
            if ((t & 31) == 0) r8[t >> 5] = m2;
            asm volatile("bar.sync 1, 64;" ::: "memory");
            Kq = fmaxf(r8[0], r8[1]);
            efo[r] = __expf(ph - Kq);
        }
        __syncthreads();                       // S3: efo visible

        // ---- g-step: column partials over own rows ----
        acc = make_float4(0.f, 0.f, 0.f, 0.f);
        #pragma unroll
        for (int k = 0; k < 16; ++k) {
            float4 f4 = EFOv[k];
            acc.x = fmaf(f4.x, rEg[k].x, acc.x);
            acc.y = fmaf(f4.y, rEg[k].y, acc.y);
            acc.z = fmaf(f4.z, rEg[k].z, acc.z);
            acc.w = fmaf(f4.w, rEg[k].w, acc.w);
        }
        float s = (acc.x + acc.y) + (acc.z + acc.w);
        float pg2 = 0.f;
        if (t < 32) {                          // rank's G2 partial
            pg2 = fmaf(efo[t], EDA[q64 + t], efo[t + 32] * EDA[q64 + t + 32]);
            #pragma unroll
            for (int o = 16; o; o >>= 1) pg2 += __shfl_xor_sync(0xffffffffu, pg2, o);
        }
        #pragma unroll
        for (int rr = 0; rr < CLU; ++rr) st_cluster_f32(pbg_addr[par], rr, s);
        if (t == 0) {
            uint32_t ka = smem_u32(&kslotB[par][q]);
            uint32_t pa2 = smem_u32(&pg2B[par][q]);
            #pragma unroll
            for (int rr = 0; rr < CLU; ++rr) {
                st_cluster_f32(ka, rr, Kq);
                st_cluster_f32(pa2, rr, pg2);
            }
        }
        CLUSTER_SYNC();                        // the ONE barrier

        if (t == 0) {                          // rescale weights + G2 (identical on all ranks)
            float k0 = kslotB[par][0], k1 = kslotB[par][1],
                  k2 = kslotB[par][2], k3 = kslotB[par][3];
            float Km = fmaxf(fmaxf(k0, k1), fmaxf(k2, k3));
            float w0 = __expf(k0 - Km), w1 = __expf(k1 - Km),
                  w2 = __expf(k2 - Km), w3 = __expf(k3 - Km);
            wv[0] = w0; wv[1] = w1; wv[2] = w2; wv[3] = w3;
            float wf2 = 256.f * __expf(sc[0] - Km);
            sc[2] = wf2; kmS = Km;
            float sg2 = ((pg2B[par][0] * w0 + pg2B[par][1] * w1)
                       + (pg2B[par][2] * w2 + pg2B[par][3] * w3)) + wf2;
            sc[1] = -(Km + __logf(sg2));
        }
        __syncthreads();                       // S4
        {
            const float* pb = pbgB[par];
            float S = ((pb[t] * wv[0] + pb[256 + t] * wv[1])
                     + (pb[512 + t] * wv[2] + pb[768 + t] * wv[3]))
                    + sc[2] * EDB[t];
            phiG = -(kmS + __logf(S));
        }
        float maxd = 1e30f;
        if (doK) {
            float dlt = fabsf(phiG - gOld);
            gOld = phiG;
            float m2 = phiG;
            #pragma unroll
            for (int o = 16; o; o >>= 1) {
                m2 = fmaxf(m2, __shfl_xor_sync(0xffffffffu, m2, o));
                dlt = fmaxf(dlt, __shfl_xor_sync(0xffffffffu, dlt, o));
            }
            if ((t & 31) == 0) { r8[w] = m2; r8d[w] = dlt; }
            __syncthreads();                   // S5
            K_G = r8[0]; maxd = r8d[0];
            #pragma unroll
            for (int k = 1; k < 8; ++k) {
                K_G = fmaxf(K_G, r8[k]);
                maxd = fmaxf(maxd, r8d[k]);
            }
        }
        EG[t] = __expf(phiG - K_G);
        if (t == 0) sc[3] = __expf(sc[1] - K_G);
        __syncthreads();                       // S6
        if (doK && it >= MIN_ITERS && maxd < EXIT_TOL) break;
    }

    Gs[t] = phiG;
    __syncthreads();

    // ---- final cost partial: own-row block of Mpp + rank-1 terms ----
    float acc2 = 0.f;
    #pragma unroll 4
    for (int ii = 0; ii < 64; ++ii) {
        float2 aq = Ash[q64 + ii];
        float cs = fmaxf(fabsf(aq.x - b.x), fabsf(aq.y - b.y)) * ie;
        acc2 += __expf(fphi[ii] + phiG - cs) * cs;
    }
    if (t < 64) {
        int i = q64 + t;
        acc2 += 256.f * __expf(fphi[t] + sc[1] - das[i]) * das[i];
        acc2 += 256.f * __expf(sc[0] + Gs[i] - dbs[i]) * dbs[i];
    }
    float tot = blkSum(acc2, r8);

    if (t == 0) {
        g_wpart[p * CLU + q] = tot * eps;
        __threadfence();
        int ticket = atomicAdd(&g_ctr, 1);
        if (ticket == NIMG * CLU - 1) {
            g_ctr = 0;
            float ssum = 0.f;
            for (int pp = 0; pp < NIMG; ++pp) {
                float w2 = 0.f;
                for (int qq = 0; qq < CLU; ++qq) w2 += g_wpart[pp * CLU + qq];
                ssum += w2;
            }
            out[0] = ssum * 0.25f;
        }
    }
}

extern "C" void kernel_launch(void* const* d_in, const int* in_sizes, int n_in,
                              void* d_out, int out_size) {
    (void)in_sizes; (void)n_in; (void)out_size;
    const float* x = (const float*)d_in[0];
    const int* y = (const int*)d_in[1];
    pool_kernel<<<(NIMG * NPX + 255) / 256, 256>>>(x, y);
    diagram_kernel<<<48, 256>>>();
    sinkhorn_kernel<<<NIMG * CLU, 256>>>((float*)d_out);
}